// round 7
// baseline (speedup 1.0000x reference)
#include <cuda_runtime.h>
#include <cuda_bf16.h>

// Chamfer loss (nearest-target-vertex): B=4, N=16384, M=4096, D=3.
// d2[b,n] = p2 + 2 * min_m (0.5*|v|^2 - p.v);  loss[b] = sum_n d2[b,n] / N
//
// Single kernel, M-split x8 (1024 blocks, 256 thr, 2 pts/thr):
//  - each block: 512 points x 512 targets, packed f32x2 FMA dot products,
//    stores CLAMPED partial d2 per split to scratch.
//  - last-arriving block per (batch,chunk) folds the 8 partials (min) and
//    accumulates; the globally-last elect block writes out[]. All counters
//    and accumulators reset to zero each launch (graph-replay safe).

#define B_ 4
#define N_ 16384
#define M_ 4096
#define SPLITS 8
#define M_PER (M_ / SPLITS)            // 512 targets per block
#define PAIRS_PER (M_PER / 2)          // 256 target pairs
#define THREADS 256
#define PPT 2
#define PTS_PER_BLOCK (THREADS * PPT)            // 512
#define CHUNKS (N_ / PTS_PER_BLOCK)              // 32
#define GRID1 (B_ * CHUNKS * SPLITS)             // 1024
#define NCHUNK_TOTAL (B_ * CHUNKS)               // 128 elect blocks
#define SMEM_BYTES (M_PER * 16)                  // 8 KB

typedef unsigned long long u64;

__device__ float g_partial[SPLITS][B_ * N_];     // 2 MB scratch (clamped d2)
__device__ int   g_chunk_cnt[NCHUNK_TOTAL];      // zero-init, self-resetting
__device__ float g_batch_sum[B_];                // zero-init, self-resetting
__device__ int   g_done;                         // zero-init, self-resetting

__device__ __forceinline__ u64 pack2(float lo, float hi) {
    u64 r;
    asm("mov.b64 %0, {%1, %2};" : "=l"(r) : "f"(lo), "f"(hi));
    return r;
}
__device__ __forceinline__ void unpack2(u64 v, float& lo, float& hi) {
    asm("mov.b64 {%0, %1}, %2;" : "=f"(lo), "=f"(hi) : "l"(v));
}
__device__ __forceinline__ u64 fma2(u64 a, u64 b, u64 c) {
    u64 d;
    asm("fma.rn.f32x2 %0, %1, %2, %3;" : "=l"(d) : "l"(a), "l"(b), "l"(c));
    return d;
}

__global__ __launch_bounds__(THREADS)
void chamfer_kernel(const float* __restrict__ src,
                    const float* __restrict__ tgt,
                    float* __restrict__ out) {
    extern __shared__ float sv[];   // 256 pairs x 32B (f32x2-ready layout)

    const int s     = blockIdx.x % SPLITS;
    const int t     = blockIdx.x / SPLITS;
    const int b     = t / CHUNKS;
    const int chunk = t % CHUNKS;

    // Load this block's 512-target tile (w = 0.5*|v|^2), pair layout:
    //   [ vx0,vx1, vy0,vy1 | vz0,vz1, w0,w1 ] per 32B pair.
    const float* tb = tgt + (size_t)b * M_ * 3 + (size_t)s * M_PER * 3;
    for (int i = threadIdx.x; i < M_PER; i += THREADS) {
        float x = tb[3 * i + 0];
        float y = tb[3 * i + 1];
        float z = tb[3 * i + 2];
        float w = 0.5f * (x * x + y * y + z * z);
        int base = (i >> 1) * 8 + (i & 1);
        sv[base + 0] = x;
        sv[base + 2] = y;
        sv[base + 4] = z;
        sv[base + 6] = w;
    }
    __syncthreads();

    // Per-thread source points, negated + broadcast into f32x2 regs.
    u64 npx2[PPT], npy2[PPT], npz2[PPT];
    float p2[PPT], mn0[PPT], mn1[PPT];
    int pidx[PPT];
#pragma unroll
    for (int p = 0; p < PPT; p++) {
        pidx[p] = b * N_ + chunk * PTS_PER_BLOCK + p * THREADS + threadIdx.x;
        float x = src[3 * pidx[p] + 0];
        float y = src[3 * pidx[p] + 1];
        float z = src[3 * pidx[p] + 2];
        npx2[p] = pack2(-x, -x);
        npy2[p] = pack2(-y, -y);
        npz2[p] = pack2(-z, -z);
        p2[p]  = x * x + y * y + z * z;
        mn0[p] = 3.4e38f;
        mn1[p] = 3.4e38f;
    }

    const ulonglong2* s2 = (const ulonglong2*)sv;
    // Per pair-iter per point: 3 FFMA2 (fma pipe) + 2 FMNMX (alu pipe).
#pragma unroll 8
    for (int j = 0; j < PAIRS_PER; j++) {
        ulonglong2 LA = s2[2 * j];       // (vx2, vy2)
        ulonglong2 LB = s2[2 * j + 1];   // (vz2, w2)
#pragma unroll
        for (int p = 0; p < PPT; p++) {
            u64 acc = fma2(LA.x, npx2[p], LB.y);
            acc = fma2(LA.y, npy2[p], acc);
            acc = fma2(LB.x, npz2[p], acc);
            float a0, a1;
            unpack2(acc, a0, a1);
            mn0[p] = fminf(mn0[p], a0);
            mn1[p] = fminf(mn1[p], a1);
        }
    }

    // Store CLAMPED partial d2 (min-fold commutes with the monotone clamp).
#pragma unroll
    for (int p = 0; p < PPT; p++) {
        float mn = fminf(mn0[p], mn1[p]);
        g_partial[s][pidx[p]] = fmaxf(fmaf(2.0f, mn, p2[p]), 0.0f);
    }

    // ---- last-block-per-chunk elect: fold the 8 splits ----
    __threadfence();                 // release our partial stores
    __shared__ int sh_last;
    if (threadIdx.x == 0) {
        int c = b * CHUNKS + chunk;
        int old = atomicAdd(&g_chunk_cnt[c], 1);
        sh_last = (old == SPLITS - 1);
        if (sh_last) g_chunk_cnt[c] = 0;   // self-reset for next replay
    }
    __syncthreads();
    if (!sh_last) return;
    __threadfence();                 // acquire others' partial stores

    float local = 0.0f;
#pragma unroll
    for (int p = 0; p < PPT; p++) {
        int i = pidx[p];
        float v0 = g_partial[0][i];
        float v1 = g_partial[1][i];
        float v2 = g_partial[2][i];
        float v3 = g_partial[3][i];
        float v4 = g_partial[4][i];
        float v5 = g_partial[5][i];
        float v6 = g_partial[6][i];
        float v7 = g_partial[7][i];
        float mn = fminf(fminf(fminf(v0, v1), fminf(v2, v3)),
                         fminf(fminf(v4, v5), fminf(v6, v7)));
        local += mn;                 // already clamped d2
    }

#pragma unroll
    for (int off = 16; off > 0; off >>= 1)
        local += __shfl_down_sync(0xffffffffu, local, off);

    __shared__ float warp_sums[THREADS / 32];
    if ((threadIdx.x & 31) == 0) warp_sums[threadIdx.x >> 5] = local;
    __syncthreads();

    if (threadIdx.x == 0) {
        float ssum = 0.0f;
#pragma unroll
        for (int wgt = 0; wgt < THREADS / 32; wgt++)
            ssum += warp_sums[wgt];
        atomicAdd(&g_batch_sum[b], ssum);
        __threadfence();             // order sum-add before done-count
        int old = atomicAdd(&g_done, 1);
        if (old == NCHUNK_TOTAL - 1) {
            g_done = 0;              // self-reset
            __threadfence();         // see all batch-sum adds
#pragma unroll
            for (int bb = 0; bb < B_; bb++) {
                out[bb] = g_batch_sum[bb] * (1.0f / N_);
                g_batch_sum[bb] = 0.0f;   // self-reset
            }
        }
    }
}

extern "C" void kernel_launch(void* const* d_in, const int* in_sizes, int n_in,
                              void* d_out, int out_size) {
    const float* src = (const float*)d_in[0];
    const float* tgt = (const float*)d_in[1];
    if (n_in >= 2 && in_sizes[0] == B_ * M_ * 3 && in_sizes[1] == B_ * N_ * 3) {
        const float* t = src; src = tgt; tgt = t;
    }
    float* out = (float*)d_out;

    chamfer_kernel<<<GRID1, THREADS, SMEM_BYTES>>>(src, tgt, out);
}